// round 3
// baseline (speedup 1.0000x reference)
#include <cuda_runtime.h>

// SpatialLoss: per-segment variance loss over batch 0 only.
// inputs: superpixels_results int32 [2,1024,1024], feats float32 [2,64,1024,1024]
// output: scalar float32.
//
// Round 3 strategy: warp-private smem histograms with PLAIN (non-atomic)
// read-modify-writes. Intra-warp same-segment collisions detected via
// __match_any_sync; rare collision lanes use smem atomicAdd (disjoint
// addresses from singleton lanes -> race free). This moves the 64M-add
// reduction off the narrow atomic ALUs (L2: ~192 adds/cyc chip-wide,
// smem ATOMS: ~1 add/cyc/SM) onto the wide smem crossbar + FP pipes.
// Global flush uses red.global.v4 but only 6.2M adds (10x less than R2).

#define NSEG    2048
#define NCH     64
#define PIX     (1024 * 1024)
#define CHUNKP  28416              // 222 iters * 128 px
#define NCHUNK  37                 // 37 * 28416 >= PIX
#define CGROUPS 16                 // 16 groups of 4 channels
#define WPB     4                  // warps per block
#define NBLOCKS 148                // one wave, 592 warp-instances = 16 * 37
#define HISTS   6                  // 4 ch sums + ssq + cnt
#define SMEM_BYTES (WPB * HISTS * NSEG * 4)   // 196608

__device__ float g_sum[NCH * NSEG];        // [ch][seg]
__device__ float g_ssqg[CGROUPS * NSEG];   // per-cgroup partial ssq (kills L2 per-addr serialization)
__device__ float g_cnt[NSEG];

__device__ __forceinline__ void red4(float* p, float4 v) {
    asm volatile("red.global.add.v4.f32 [%0], {%1,%2,%3,%4};"
                 :: "l"(p), "f"(v.x), "f"(v.y), "f"(v.z), "f"(v.w) : "memory");
}

__global__ void zero_kernel() {
    int i = blockIdx.x * blockDim.x + threadIdx.x;
    if (i < NCH * NSEG) g_sum[i] = 0.0f;
    int j = i - NCH * NSEG;
    if (j >= 0 && j < CGROUPS * NSEG) g_ssqg[j] = 0.0f;
    int k = j - CGROUPS * NSEG;
    if (k >= 0 && k < NSEG) g_cnt[k] = 0.0f;
}

#define STEP(S, VA, VB, VC, VD) do {                                          \
    const int _s = (S);                                                       \
    const unsigned _m = __match_any_sync(0xffffffffu, _s);                    \
    const float _q = (VA)*(VA) + (VB)*(VB) + (VC)*(VC) + (VD)*(VD);           \
    if (_m == (1u << lane)) {                                                 \
        h0[_s] += (VA); h1[_s] += (VB); h2[_s] += (VC); h3[_s] += (VD);       \
        hq[_s] += _q;                                                         \
        if (docnt) hc[_s] += 1.0f;                                            \
    } else {                                                                  \
        atomicAdd(&h0[_s], (VA)); atomicAdd(&h1[_s], (VB));                   \
        atomicAdd(&h2[_s], (VC)); atomicAdd(&h3[_s], (VD));                   \
        atomicAdd(&hq[_s], _q);                                               \
        if (docnt) atomicAdd(&hc[_s], 1.0f);                                  \
    }                                                                         \
} while (0)

__global__ __launch_bounds__(128, 1)
void accum_kernel(const int* __restrict__ sp, const float* __restrict__ feats) {
    extern __shared__ float smem[];
    const int lane   = threadIdx.x & 31;
    const int warpid = threadIdx.x >> 5;

    float* h0 = smem + warpid * (HISTS * NSEG);
    float* h1 = h0 + NSEG;
    float* h2 = h0 + 2 * NSEG;
    float* h3 = h0 + 3 * NSEG;
    float* hq = h0 + 4 * NSEG;
    float* hc = h0 + 5 * NSEG;

    {   // zero this warp's private hists
        const float4 z = make_float4(0.f, 0.f, 0.f, 0.f);
        float4* hv = (float4*)h0;
        for (int i = lane; i < HISTS * NSEG / 4; i += 32) hv[i] = z;
    }
    __syncwarp();

    const int  W     = blockIdx.x * WPB + warpid;   // 0..591
    const int  cg    = W & 15;                      // channel quad
    const int  chunk = W >> 4;                      // 0..36
    const bool docnt = (cg == 0);

    const float* f0 = feats + (size_t)(cg * 4 + 0) * PIX;
    const float* f1 = feats + (size_t)(cg * 4 + 1) * PIX;
    const float* f2 = feats + (size_t)(cg * 4 + 2) * PIX;
    const float* f3 = feats + (size_t)(cg * 4 + 3) * PIX;

    const int base  = chunk * CHUNKP;
    int niter = (PIX - base) >> 7;                  // 128 px per warp-iter
    if (niter > CHUNKP / 128) niter = CHUNKP / 128; // 222

    int p = base + lane * 4;
    int4   s4 = *(const int4*)(sp + p);
    float4 a  = *(const float4*)(f0 + p);
    float4 b  = *(const float4*)(f1 + p);
    float4 c  = *(const float4*)(f2 + p);
    float4 d  = *(const float4*)(f3 + p);

    for (int it = 0; it < niter; it++) {
        int4 ns = s4; float4 na = a, nb = b, nc = c, nd = d;
        if (it + 1 < niter) {   // prefetch next iter (uniform predicate)
            const int np = p + 128;
            ns = *(const int4*)(sp + np);
            na = *(const float4*)(f0 + np);
            nb = *(const float4*)(f1 + np);
            nc = *(const float4*)(f2 + np);
            nd = *(const float4*)(f3 + np);
        }
        STEP(s4.x, a.x, b.x, c.x, d.x);
        STEP(s4.y, a.y, b.y, c.y, d.y);
        STEP(s4.z, a.z, b.z, c.z, d.z);
        STEP(s4.w, a.w, b.w, c.w, d.w);
        p += 128; s4 = ns; a = na; b = nb; c = nc; d = nd;
    }
    __syncwarp();

    // flush private hists to global via L2 vector reductions
    for (int i = lane; i < NSEG / 4; i += 32) {
        red4(&g_sum[(cg * 4 + 0) * NSEG + i * 4], ((float4*)h0)[i]);
        red4(&g_sum[(cg * 4 + 1) * NSEG + i * 4], ((float4*)h1)[i]);
        red4(&g_sum[(cg * 4 + 2) * NSEG + i * 4], ((float4*)h2)[i]);
        red4(&g_sum[(cg * 4 + 3) * NSEG + i * 4], ((float4*)h3)[i]);
        red4(&g_ssqg[cg * NSEG + i * 4],          ((float4*)hq)[i]);
        if (docnt) red4(&g_cnt[i * 4],            ((float4*)hc)[i]);
    }
}

__global__ void finalize_kernel(float* __restrict__ out) {
    __shared__ float red_loss[1024];
    __shared__ float red_cnt[1024];
    const int tid = threadIdx.x;
    float loss = 0.0f, nz = 0.0f;
    for (int seg = tid; seg < NSEG; seg += 1024) {
        const float n = g_cnt[seg];
        float ssq = 0.0f;
        #pragma unroll
        for (int g = 0; g < CGROUPS; g++) ssq += g_ssqg[g * NSEG + seg];
        float s2 = 0.0f;
        #pragma unroll
        for (int ch = 0; ch < NCH; ch++) {
            const float s = g_sum[ch * NSEG + seg];
            s2 += s * s;
        }
        const float nn = fmaxf(n, 1.0f);
        const float var_sum = ssq - s2 / nn;
        const float per_seg = var_sum / ((float)NCH * nn);
        if (n >= 2.0f) loss += per_seg;
        if (n > 0.0f)  nz += 1.0f;
    }
    red_loss[tid] = loss;
    red_cnt[tid]  = nz;
    __syncthreads();
    for (int s = 512; s > 0; s >>= 1) {
        if (tid < s) {
            red_loss[tid] += red_loss[tid + s];
            red_cnt[tid]  += red_cnt[tid + s];
        }
        __syncthreads();
    }
    if (tid == 0) out[0] = red_loss[0] / red_cnt[0];
}

extern "C" void kernel_launch(void* const* d_in, const int* in_sizes, int n_in,
                              void* d_out, int out_size) {
    const int* sp;
    const float* feats;
    if (in_sizes[0] == 2 * 1024 * 1024) {
        sp    = (const int*)d_in[0];
        feats = (const float*)d_in[1];
    } else {
        sp    = (const int*)d_in[1];
        feats = (const float*)d_in[0];
    }

    cudaFuncSetAttribute(accum_kernel,
                         cudaFuncAttributeMaxDynamicSharedMemorySize, SMEM_BYTES);

    const int zero_total = (NCH + CGROUPS + 1) * NSEG;
    zero_kernel<<<(zero_total + 255) / 256, 256>>>();

    accum_kernel<<<NBLOCKS, WPB * 32, SMEM_BYTES>>>(sp, feats);

    finalize_kernel<<<1, 1024>>>((float*)d_out);
}

// round 4
// speedup vs baseline: 3.2215x; 3.2215x over previous
#include <cuda_runtime.h>
#include <cuda_fp16.h>

// SpatialLoss: per-segment variance loss over batch 0 only.
// inputs: superpixels_results int32 [2,1024,1024], feats float32 [2,64,1024,1024]
// output: scalar float32.
//
// Round 4: fp16x2-packed L2 reductions. The L2 atomic ALU is the wall
// (~1 fp32 add / cyc / partition); packing 2 channel-adds per 32-bit lane
// via red.global.add.noftz.v4.f16x2 halves the add currency (64M -> 32M
// u32-units) and cuts RED issue count 4x vs scalar.

#define NSEG    2048
#define NCH     64
#define NPAIR   (NCH / 2)          // 32 half2 pairs per segment
#define PIX     (1024 * 1024)
#define THREADS 256

__device__ __align__(16) __half2 g_sumh[NSEG * NPAIR];  // [seg][pair], pair=(2i,2i+1)
__device__ float2 g_sc[NSEG];                           // (ssq over all ch, count)

__device__ __forceinline__ void red8(__half2* p, __half2 a, __half2 b,
                                     __half2 c, __half2 d) {
    asm volatile("red.global.add.noftz.v4.f16x2 [%0], {%1,%2,%3,%4};"
                 :: "l"(p),
                    "r"(*(const unsigned*)&a), "r"(*(const unsigned*)&b),
                    "r"(*(const unsigned*)&c), "r"(*(const unsigned*)&d)
                 : "memory");
}
__device__ __forceinline__ void red2(float2* p, float a, float b) {
    asm volatile("red.global.add.v2.f32 [%0], {%1, %2};"
                 :: "l"(p), "f"(a), "f"(b) : "memory");
}

__global__ void zero_kernel() {
    int i = blockIdx.x * blockDim.x + threadIdx.x;
    if (i < NSEG * NPAIR) ((unsigned*)g_sumh)[i] = 0u;   // half2(0,0)
    int j = i - NSEG * NPAIR;
    if (j >= 0 && j < NSEG) g_sc[j] = make_float2(0.0f, 0.0f);
}

__global__ __launch_bounds__(THREADS)
void accum_kernel(const int* __restrict__ sp, const float* __restrict__ feats) {
    const int t = blockIdx.x * THREADS + threadIdx.x;
    const int p = t * 4;                      // 4 consecutive pixels per thread

    const int4 s4 = *(const int4*)(sp + p);
    __half2* r0 = g_sumh + (size_t)s4.x * NPAIR;
    __half2* r1 = g_sumh + (size_t)s4.y * NPAIR;
    __half2* r2 = g_sumh + (size_t)s4.z * NPAIR;
    __half2* r3 = g_sumh + (size_t)s4.w * NPAIR;

    __half2 q0 = __float2half2_rn(0.0f);
    __half2 q1 = q0, q2 = q0, q3 = q0;

    #pragma unroll
    for (int oct = 0; oct < 8; oct++) {       // 8 channels per oct
        const float* f = feats + (size_t)(oct * 8) * PIX + p;
        float4 v0 = *(const float4*)(f + 0 * (size_t)PIX);
        float4 v1 = *(const float4*)(f + 1 * (size_t)PIX);
        float4 v2 = *(const float4*)(f + 2 * (size_t)PIX);
        float4 v3 = *(const float4*)(f + 3 * (size_t)PIX);
        float4 v4 = *(const float4*)(f + 4 * (size_t)PIX);
        float4 v5 = *(const float4*)(f + 5 * (size_t)PIX);
        float4 v6 = *(const float4*)(f + 6 * (size_t)PIX);
        float4 v7 = *(const float4*)(f + 7 * (size_t)PIX);

        // pixel 0 (.x lanes): 4 channel-pairs -> one 16B vector RED
        {
            __half2 a = __floats2half2_rn(v0.x, v1.x);
            __half2 b = __floats2half2_rn(v2.x, v3.x);
            __half2 c = __floats2half2_rn(v4.x, v5.x);
            __half2 d = __floats2half2_rn(v6.x, v7.x);
            q0 = __hfma2(a, a, q0); q0 = __hfma2(b, b, q0);
            q0 = __hfma2(c, c, q0); q0 = __hfma2(d, d, q0);
            red8(r0 + oct * 4, a, b, c, d);
        }
        {   // pixel 1
            __half2 a = __floats2half2_rn(v0.y, v1.y);
            __half2 b = __floats2half2_rn(v2.y, v3.y);
            __half2 c = __floats2half2_rn(v4.y, v5.y);
            __half2 d = __floats2half2_rn(v6.y, v7.y);
            q1 = __hfma2(a, a, q1); q1 = __hfma2(b, b, q1);
            q1 = __hfma2(c, c, q1); q1 = __hfma2(d, d, q1);
            red8(r1 + oct * 4, a, b, c, d);
        }
        {   // pixel 2
            __half2 a = __floats2half2_rn(v0.z, v1.z);
            __half2 b = __floats2half2_rn(v2.z, v3.z);
            __half2 c = __floats2half2_rn(v4.z, v5.z);
            __half2 d = __floats2half2_rn(v6.z, v7.z);
            q2 = __hfma2(a, a, q2); q2 = __hfma2(b, b, q2);
            q2 = __hfma2(c, c, q2); q2 = __hfma2(d, d, q2);
            red8(r2 + oct * 4, a, b, c, d);
        }
        {   // pixel 3
            __half2 a = __floats2half2_rn(v0.w, v1.w);
            __half2 b = __floats2half2_rn(v2.w, v3.w);
            __half2 c = __floats2half2_rn(v4.w, v5.w);
            __half2 d = __floats2half2_rn(v6.w, v7.w);
            q3 = __hfma2(a, a, q3); q3 = __hfma2(b, b, q3);
            q3 = __hfma2(c, c, q3); q3 = __hfma2(d, d, q3);
            red8(r3 + oct * 4, a, b, c, d);
        }
    }

    red2(&g_sc[s4.x], __low2float(q0) + __high2float(q0), 1.0f);
    red2(&g_sc[s4.y], __low2float(q1) + __high2float(q1), 1.0f);
    red2(&g_sc[s4.z], __low2float(q2) + __high2float(q2), 1.0f);
    red2(&g_sc[s4.w], __low2float(q3) + __high2float(q3), 1.0f);
}

__global__ void finalize_kernel(float* __restrict__ out) {
    __shared__ float red_loss[1024];
    __shared__ float red_cnt[1024];
    const int tid = threadIdx.x;
    float loss = 0.0f, nz = 0.0f;
    for (int seg = tid; seg < NSEG; seg += 1024) {
        const float2 sc = g_sc[seg];
        const float n   = sc.y;
        const float ssq = sc.x;
        float s2 = 0.0f;
        #pragma unroll
        for (int i = 0; i < NPAIR; i++) {
            const float2 s = __half22float2(g_sumh[seg * NPAIR + i]);
            s2 += s.x * s.x + s.y * s.y;
        }
        const float nn = fmaxf(n, 1.0f);
        const float var_sum = ssq - s2 / nn;
        const float per_seg = var_sum / ((float)NCH * nn);
        if (n >= 2.0f) loss += per_seg;
        if (n > 0.0f)  nz += 1.0f;
    }
    red_loss[tid] = loss;
    red_cnt[tid]  = nz;
    __syncthreads();
    for (int s = 512; s > 0; s >>= 1) {
        if (tid < s) {
            red_loss[tid] += red_loss[tid + s];
            red_cnt[tid]  += red_cnt[tid + s];
        }
        __syncthreads();
    }
    if (tid == 0) out[0] = red_loss[0] / red_cnt[0];
}

extern "C" void kernel_launch(void* const* d_in, const int* in_sizes, int n_in,
                              void* d_out, int out_size) {
    const int* sp;
    const float* feats;
    if (in_sizes[0] == 2 * 1024 * 1024) {
        sp    = (const int*)d_in[0];
        feats = (const float*)d_in[1];
    } else {
        sp    = (const int*)d_in[1];
        feats = (const float*)d_in[0];
    }

    const int zero_total = NSEG * NPAIR + NSEG;
    zero_kernel<<<(zero_total + 255) / 256, 256>>>();

    accum_kernel<<<(PIX / 4) / THREADS, THREADS>>>(sp, feats);

    finalize_kernel<<<1, 1024>>>((float*)d_out);
}

// round 5
// speedup vs baseline: 3.2520x; 1.0095x over previous
#include <cuda_runtime.h>
#include <cuda_fp16.h>

// SpatialLoss: per-segment variance loss over batch 0 only.
// inputs: superpixels_results int32 [2,1024,1024], feats float32 [2,64,1024,1024]
// output: scalar float32.
//
// Round 5: hybrid reduction. Channels 0..23 accumulate in per-block SMEM
// f16x2 histograms (native ATOMS.ADD.F16x2, ~148 ops/cyc chip-wide);
// channels 24..63 go through L2 red.v4.f16x2 (~192 lanes/cyc chip-wide).
// Both atomic units run concurrently. SMEM hists are flushed with plain
// STG to a per-block slab and reduced by a separate kernel (no atomics).

#define NSEG     2048
#define PIX      (1024 * 1024)
#define TPB      512
#define NBLK     256
#define SPAIRS   12                    // f16x2 units per px in smem (24 ch)
#define LUNITS   20                    // f16x2 units per px on L2 (40 ch)
#define SMEM_U32 (SPAIRS * NSEG)       // 24576 u32 = 96KB

__device__ __half2 g_sumh[NSEG * LUNITS];          // [seg][unit], L2 RED target
__device__ float2  g_sc[NSEG];                     // (ssq, count)
__device__ __half2 g_part[(size_t)NBLK * SMEM_U32];// per-block smem hist dumps
__device__ float2  g_sum32[SPAIRS * NSEG];         // reduced fp32 sums, [pair][seg]

__device__ __forceinline__ void red8(__half2* p, __half2 a, __half2 b,
                                     __half2 c, __half2 d) {
    asm volatile("red.global.add.noftz.v4.f16x2 [%0], {%1,%2,%3,%4};"
                 :: "l"(p),
                    "r"(*(const unsigned*)&a), "r"(*(const unsigned*)&b),
                    "r"(*(const unsigned*)&c), "r"(*(const unsigned*)&d)
                 : "memory");
}
__device__ __forceinline__ void red2(float2* p, float a, float b) {
    asm volatile("red.global.add.v2.f32 [%0], {%1, %2};"
                 :: "l"(p), "f"(a), "f"(b) : "memory");
}

__global__ void zero_kernel() {
    int i = blockIdx.x * blockDim.x + threadIdx.x;
    if (i < NSEG * LUNITS) ((unsigned*)g_sumh)[i] = 0u;
    int j = i - NSEG * LUNITS;
    if (j >= 0 && j < NSEG) g_sc[j] = make_float2(0.0f, 0.0f);
}

template <int OCT>
__device__ __forceinline__ void do_pixel(int s, __half2 a, __half2 b,
                                         __half2 c, __half2 d,
                                         __half2& q, __half2* sh) {
    q = __hfma2(a, a, q); q = __hfma2(b, b, q);
    q = __hfma2(c, c, q); q = __hfma2(d, d, q);
    if (OCT < 3) {
        atomicAdd(&sh[(OCT * 4 + 0) * NSEG + s], a);
        atomicAdd(&sh[(OCT * 4 + 1) * NSEG + s], b);
        atomicAdd(&sh[(OCT * 4 + 2) * NSEG + s], c);
        atomicAdd(&sh[(OCT * 4 + 3) * NSEG + s], d);
    } else {
        red8(&g_sumh[(size_t)s * LUNITS + (OCT - 3) * 4], a, b, c, d);
    }
}

template <int OCT>
__device__ __forceinline__ void do_oct(const float* __restrict__ feats, int p,
                                       const int4 s4, __half2& q0, __half2& q1,
                                       __half2& q2, __half2& q3, __half2* sh) {
    const float* f = feats + (size_t)(OCT * 8) * PIX + p;
    const float4 v0 = *(const float4*)(f + 0 * (size_t)PIX);
    const float4 v1 = *(const float4*)(f + 1 * (size_t)PIX);
    const float4 v2 = *(const float4*)(f + 2 * (size_t)PIX);
    const float4 v3 = *(const float4*)(f + 3 * (size_t)PIX);
    const float4 v4 = *(const float4*)(f + 4 * (size_t)PIX);
    const float4 v5 = *(const float4*)(f + 5 * (size_t)PIX);
    const float4 v6 = *(const float4*)(f + 6 * (size_t)PIX);
    const float4 v7 = *(const float4*)(f + 7 * (size_t)PIX);

    do_pixel<OCT>(s4.x, __floats2half2_rn(v0.x, v1.x), __floats2half2_rn(v2.x, v3.x),
                  __floats2half2_rn(v4.x, v5.x), __floats2half2_rn(v6.x, v7.x), q0, sh);
    do_pixel<OCT>(s4.y, __floats2half2_rn(v0.y, v1.y), __floats2half2_rn(v2.y, v3.y),
                  __floats2half2_rn(v4.y, v5.y), __floats2half2_rn(v6.y, v7.y), q1, sh);
    do_pixel<OCT>(s4.z, __floats2half2_rn(v0.z, v1.z), __floats2half2_rn(v2.z, v3.z),
                  __floats2half2_rn(v4.z, v5.z), __floats2half2_rn(v6.z, v7.z), q2, sh);
    do_pixel<OCT>(s4.w, __floats2half2_rn(v0.w, v1.w), __floats2half2_rn(v2.w, v3.w),
                  __floats2half2_rn(v4.w, v5.w), __floats2half2_rn(v6.w, v7.w), q3, sh);
}

__global__ __launch_bounds__(TPB, 2)
void accum_kernel(const int* __restrict__ sp, const float* __restrict__ feats) {
    extern __shared__ __half2 sh[];    // [SPAIRS][NSEG]

    {   // zero smem hist
        uint4* z = (uint4*)sh;
        #pragma unroll
        for (int i = threadIdx.x; i < SMEM_U32 / 4; i += TPB)
            z[i] = make_uint4(0u, 0u, 0u, 0u);
    }
    __syncthreads();

    #pragma unroll
    for (int g = 0; g < 2; g++) {
        const int grp = g * (NBLK * TPB) + blockIdx.x * TPB + threadIdx.x;
        const int p = grp * 4;
        const int4 s4 = *(const int4*)(sp + p);
        __half2 q0 = __float2half2_rn(0.0f), q1 = q0, q2 = q0, q3 = q0;

        do_oct<0>(feats, p, s4, q0, q1, q2, q3, sh);
        do_oct<1>(feats, p, s4, q0, q1, q2, q3, sh);
        do_oct<2>(feats, p, s4, q0, q1, q2, q3, sh);
        do_oct<3>(feats, p, s4, q0, q1, q2, q3, sh);
        do_oct<4>(feats, p, s4, q0, q1, q2, q3, sh);
        do_oct<5>(feats, p, s4, q0, q1, q2, q3, sh);
        do_oct<6>(feats, p, s4, q0, q1, q2, q3, sh);
        do_oct<7>(feats, p, s4, q0, q1, q2, q3, sh);

        red2(&g_sc[s4.x], __low2float(q0) + __high2float(q0), 1.0f);
        red2(&g_sc[s4.y], __low2float(q1) + __high2float(q1), 1.0f);
        red2(&g_sc[s4.z], __low2float(q2) + __high2float(q2), 1.0f);
        red2(&g_sc[s4.w], __low2float(q3) + __high2float(q3), 1.0f);
    }
    __syncthreads();

    // flush smem hist to per-block slab with plain vector stores (no atomics)
    const uint4* src = (const uint4*)sh;
    uint4* dst = (uint4*)(g_part + (size_t)blockIdx.x * SMEM_U32);
    #pragma unroll
    for (int i = threadIdx.x; i < SMEM_U32 / 4; i += TPB)
        dst[i] = src[i];
}

__global__ void reduce_kernel() {
    // one thread per (pair, seg): sum 256 per-block f16x2 partials in fp32
    const int i = blockIdx.x * blockDim.x + threadIdx.x;   // 0..SMEM_U32-1
    if (i >= SMEM_U32) return;
    float ax = 0.0f, ay = 0.0f;
    #pragma unroll 8
    for (int b = 0; b < NBLK; b++) {
        const float2 v = __half22float2(g_part[(size_t)b * SMEM_U32 + i]);
        ax += v.x; ay += v.y;
    }
    g_sum32[i] = make_float2(ax, ay);
}

__global__ void finalize_kernel(float* __restrict__ out) {
    __shared__ float red_loss[1024];
    __shared__ float red_cnt[1024];
    const int tid = threadIdx.x;
    float loss = 0.0f, nz = 0.0f;
    for (int seg = tid; seg < NSEG; seg += 1024) {
        const float2 sc = g_sc[seg];
        const float n   = sc.y;
        const float ssq = sc.x;
        float s2 = 0.0f;
        #pragma unroll
        for (int j = 0; j < SPAIRS; j++) {
            const float2 s = g_sum32[j * NSEG + seg];
            s2 += s.x * s.x + s.y * s.y;
        }
        #pragma unroll
        for (int u = 0; u < LUNITS; u++) {
            const float2 s = __half22float2(g_sumh[(size_t)seg * LUNITS + u]);
            s2 += s.x * s.x + s.y * s.y;
        }
        const float nn = fmaxf(n, 1.0f);
        const float var_sum = ssq - s2 / nn;
        const float per_seg = var_sum / (64.0f * nn);
        if (n >= 2.0f) loss += per_seg;
        if (n > 0.0f)  nz += 1.0f;
    }
    red_loss[tid] = loss;
    red_cnt[tid]  = nz;
    __syncthreads();
    for (int s = 512; s > 0; s >>= 1) {
        if (tid < s) {
            red_loss[tid] += red_loss[tid + s];
            red_cnt[tid]  += red_cnt[tid + s];
        }
        __syncthreads();
    }
    if (tid == 0) out[0] = red_loss[0] / red_cnt[0];
}

extern "C" void kernel_launch(void* const* d_in, const int* in_sizes, int n_in,
                              void* d_out, int out_size) {
    const int* sp;
    const float* feats;
    if (in_sizes[0] == 2 * 1024 * 1024) {
        sp    = (const int*)d_in[0];
        feats = (const float*)d_in[1];
    } else {
        sp    = (const int*)d_in[1];
        feats = (const float*)d_in[0];
    }

    const int smem_bytes = SMEM_U32 * 4;   // 98304
    cudaFuncSetAttribute(accum_kernel,
                         cudaFuncAttributeMaxDynamicSharedMemorySize, smem_bytes);

    const int zero_total = NSEG * LUNITS + NSEG;
    zero_kernel<<<(zero_total + 255) / 256, 256>>>();

    accum_kernel<<<NBLK, TPB, smem_bytes>>>(sp, feats);

    reduce_kernel<<<(SMEM_U32 + 255) / 256, 256>>>();

    finalize_kernel<<<1, 1024>>>((float*)d_out);
}

// round 6
// speedup vs baseline: 3.2661x; 1.0043x over previous
#include <cuda_runtime.h>
#include <cuda_fp16.h>

// SpatialLoss: per-segment variance loss over batch 0 only.
// Round 6: accum is FMA-pipe bound (32 F2FP + 32 HFMA2 per px). Fixes:
//  - perfectly SM-balanced 296-block grid (was: 20 SMs idle)
//  - smem/L2 atomic split rebalanced to 16ch smem / 48ch L2 (both under fma wall)
//  - reduce kernel folds s^2 into per-seg scalar via L2 RED; finalize reads 24KB.

#define NSEG     2048
#define PIX      (1024 * 1024)
#define TPB      512
#define NBLK     296
#define TOTG     (PIX / 4)             // 262144 pixel-groups of 4
#define SPAIRS   8                     // f16x2 units per px in smem (16 ch)
#define LUNITS   24                    // f16x2 units per px on L2 (48 ch)
#define SMEM_U32 (SPAIRS * NSEG)       // 16384 u32 = 64KB

__device__ __half2 g_sumh[NSEG * LUNITS];            // [seg][unit], L2 RED target
__device__ float2  g_sc[NSEG];                       // (ssq, count)
__device__ float   g_s2[NSEG];                       // sum over ch of (seg sum)^2
__device__ __half2 g_part[(size_t)NBLK * SMEM_U32];  // per-block smem hist dumps

__device__ __forceinline__ void red8(__half2* p, __half2 a, __half2 b,
                                     __half2 c, __half2 d) {
    asm volatile("red.global.add.noftz.v4.f16x2 [%0], {%1,%2,%3,%4};"
                 :: "l"(p),
                    "r"(*(const unsigned*)&a), "r"(*(const unsigned*)&b),
                    "r"(*(const unsigned*)&c), "r"(*(const unsigned*)&d)
                 : "memory");
}
__device__ __forceinline__ void red2(float2* p, float a, float b) {
    asm volatile("red.global.add.v2.f32 [%0], {%1, %2};"
                 :: "l"(p), "f"(a), "f"(b) : "memory");
}
__device__ __forceinline__ void red1(float* p, float a) {
    asm volatile("red.global.add.f32 [%0], %1;" :: "l"(p), "f"(a) : "memory");
}

__global__ void zero_kernel() {
    int i = blockIdx.x * blockDim.x + threadIdx.x;
    if (i < NSEG * LUNITS) ((unsigned*)g_sumh)[i] = 0u;
    int j = i - NSEG * LUNITS;
    if (j >= 0 && j < NSEG) { g_sc[j] = make_float2(0.0f, 0.0f); g_s2[j] = 0.0f; }
}

template <int OCT>
__device__ __forceinline__ void do_pixel(int s, __half2 a, __half2 b,
                                         __half2 c, __half2 d,
                                         __half2& q, __half2* sh) {
    q = __hfma2(a, a, q); q = __hfma2(b, b, q);
    q = __hfma2(c, c, q); q = __hfma2(d, d, q);
    if (OCT < 2) {
        atomicAdd(&sh[(OCT * 4 + 0) * NSEG + s], a);
        atomicAdd(&sh[(OCT * 4 + 1) * NSEG + s], b);
        atomicAdd(&sh[(OCT * 4 + 2) * NSEG + s], c);
        atomicAdd(&sh[(OCT * 4 + 3) * NSEG + s], d);
    } else {
        red8(&g_sumh[(size_t)s * LUNITS + (OCT - 2) * 4], a, b, c, d);
    }
}

template <int OCT>
__device__ __forceinline__ void do_oct(const float* __restrict__ feats, int p,
                                       const int4 s4, __half2& q0, __half2& q1,
                                       __half2& q2, __half2& q3, __half2* sh) {
    const float* f = feats + (size_t)(OCT * 8) * PIX + p;
    const float4 v0 = *(const float4*)(f + 0 * (size_t)PIX);
    const float4 v1 = *(const float4*)(f + 1 * (size_t)PIX);
    const float4 v2 = *(const float4*)(f + 2 * (size_t)PIX);
    const float4 v3 = *(const float4*)(f + 3 * (size_t)PIX);
    const float4 v4 = *(const float4*)(f + 4 * (size_t)PIX);
    const float4 v5 = *(const float4*)(f + 5 * (size_t)PIX);
    const float4 v6 = *(const float4*)(f + 6 * (size_t)PIX);
    const float4 v7 = *(const float4*)(f + 7 * (size_t)PIX);

    do_pixel<OCT>(s4.x, __floats2half2_rn(v0.x, v1.x), __floats2half2_rn(v2.x, v3.x),
                  __floats2half2_rn(v4.x, v5.x), __floats2half2_rn(v6.x, v7.x), q0, sh);
    do_pixel<OCT>(s4.y, __floats2half2_rn(v0.y, v1.y), __floats2half2_rn(v2.y, v3.y),
                  __floats2half2_rn(v4.y, v5.y), __floats2half2_rn(v6.y, v7.y), q1, sh);
    do_pixel<OCT>(s4.z, __floats2half2_rn(v0.z, v1.z), __floats2half2_rn(v2.z, v3.z),
                  __floats2half2_rn(v4.z, v5.z), __floats2half2_rn(v6.z, v7.z), q2, sh);
    do_pixel<OCT>(s4.w, __floats2half2_rn(v0.w, v1.w), __floats2half2_rn(v2.w, v3.w),
                  __floats2half2_rn(v4.w, v5.w), __floats2half2_rn(v6.w, v7.w), q3, sh);
}

__global__ __launch_bounds__(TPB, 2)
void accum_kernel(const int* __restrict__ sp, const float* __restrict__ feats) {
    extern __shared__ __half2 sh[];    // [SPAIRS][NSEG]

    {   // zero smem hist
        uint4* z = (uint4*)sh;
        #pragma unroll
        for (int i = threadIdx.x; i < SMEM_U32 / 4; i += TPB)
            z[i] = make_uint4(0u, 0u, 0u, 0u);
    }
    __syncthreads();

    // balanced group range for this block: ~885-886 groups each
    const int gstart = (int)(((long long)blockIdx.x       * TOTG) / NBLK);
    const int gend   = (int)(((long long)(blockIdx.x + 1) * TOTG) / NBLK);

    for (int g = gstart + threadIdx.x; g < gend; g += TPB) {
        const int p = g * 4;
        const int4 s4 = *(const int4*)(sp + p);
        __half2 q0 = __float2half2_rn(0.0f), q1 = q0, q2 = q0, q3 = q0;

        do_oct<0>(feats, p, s4, q0, q1, q2, q3, sh);
        do_oct<1>(feats, p, s4, q0, q1, q2, q3, sh);
        do_oct<2>(feats, p, s4, q0, q1, q2, q3, sh);
        do_oct<3>(feats, p, s4, q0, q1, q2, q3, sh);
        do_oct<4>(feats, p, s4, q0, q1, q2, q3, sh);
        do_oct<5>(feats, p, s4, q0, q1, q2, q3, sh);
        do_oct<6>(feats, p, s4, q0, q1, q2, q3, sh);
        do_oct<7>(feats, p, s4, q0, q1, q2, q3, sh);

        red2(&g_sc[s4.x], __low2float(q0) + __high2float(q0), 1.0f);
        red2(&g_sc[s4.y], __low2float(q1) + __high2float(q1), 1.0f);
        red2(&g_sc[s4.z], __low2float(q2) + __high2float(q2), 1.0f);
        red2(&g_sc[s4.w], __low2float(q3) + __high2float(q3), 1.0f);
    }
    __syncthreads();

    // flush smem hist to per-block slab with plain vector stores (no atomics)
    const uint4* src = (const uint4*)sh;
    uint4* dst = (uint4*)(g_part + (size_t)blockIdx.x * SMEM_U32);
    #pragma unroll
    for (int i = threadIdx.x; i < SMEM_U32 / 4; i += TPB)
        dst[i] = src[i];
}

__global__ void reduce_kernel() {
    const int i = blockIdx.x * blockDim.x + threadIdx.x;
    if (i < SMEM_U32) {
        // smem-path channel pair: sum 296 per-block f16x2 partials in fp32
        const int seg = i & (NSEG - 1);
        float a0 = 0.f, a1 = 0.f, b0 = 0.f, b1 = 0.f;
        #pragma unroll 4
        for (int b = 0; b < NBLK; b += 2) {
            const float2 u = __half22float2(g_part[(size_t)b * SMEM_U32 + i]);
            const float2 v = __half22float2(g_part[(size_t)(b + 1) * SMEM_U32 + i]);
            a0 += u.x; a1 += u.y; b0 += v.x; b1 += v.y;
        }
        const float sx = a0 + b0, sy = a1 + b1;
        red1(&g_s2[seg], sx * sx + sy * sy);
    } else {
        // L2-path channel pair: square the accumulated f16x2 sum
        const int j = i - SMEM_U32;
        if (j < NSEG * LUNITS) {
            const int seg = j / LUNITS;
            const float2 s = __half22float2(g_sumh[j]);
            red1(&g_s2[seg], s.x * s.x + s.y * s.y);
        }
    }
}

__global__ void finalize_kernel(float* __restrict__ out) {
    __shared__ float red_loss[1024];
    __shared__ float red_cnt[1024];
    const int tid = threadIdx.x;
    float loss = 0.0f, nz = 0.0f;
    #pragma unroll
    for (int seg = tid; seg < NSEG; seg += 1024) {
        const float2 sc = g_sc[seg];
        const float n   = sc.y;
        const float nn  = fmaxf(n, 1.0f);
        const float var_sum = sc.x - g_s2[seg] / nn;
        const float per_seg = var_sum / (64.0f * nn);
        if (n >= 2.0f) loss += per_seg;
        if (n > 0.0f)  nz += 1.0f;
    }
    red_loss[tid] = loss;
    red_cnt[tid]  = nz;
    __syncthreads();
    for (int s = 512; s > 0; s >>= 1) {
        if (tid < s) {
            red_loss[tid] += red_loss[tid + s];
            red_cnt[tid]  += red_cnt[tid + s];
        }
        __syncthreads();
    }
    if (tid == 0) out[0] = red_loss[0] / red_cnt[0];
}

extern "C" void kernel_launch(void* const* d_in, const int* in_sizes, int n_in,
                              void* d_out, int out_size) {
    const int* sp;
    const float* feats;
    if (in_sizes[0] == 2 * 1024 * 1024) {
        sp    = (const int*)d_in[0];
        feats = (const float*)d_in[1];
    } else {
        sp    = (const int*)d_in[1];
        feats = (const float*)d_in[0];
    }

    const int smem_bytes = SMEM_U32 * 4;   // 65536
    cudaFuncSetAttribute(accum_kernel,
                         cudaFuncAttributeMaxDynamicSharedMemorySize, smem_bytes);

    const int zero_total = NSEG * LUNITS + NSEG;          // covers g_sc + g_s2 branch
    zero_kernel<<<(zero_total + 255) / 256, 256>>>();

    accum_kernel<<<NBLK, TPB, smem_bytes>>>(sp, feats);

    const int red_total = SMEM_U32 + NSEG * LUNITS;       // 65536
    reduce_kernel<<<(red_total + 255) / 256, 256>>>();

    finalize_kernel<<<1, 1024>>>((float*)d_out);
}

// round 7
// speedup vs baseline: 3.2670x; 1.0003x over previous
#include <cuda_runtime.h>
#include <cuda_fp16.h>

// SpatialLoss: per-segment variance loss over batch 0 only.
// Round 7: register-lean inner loop (two 4-channel stages per oct) so the
// __launch_bounds__(512,2) 64-reg cap causes NO local-memory spills.
// Split: 24 ch -> per-block smem f16x2 hist (ATOMS), 40 ch -> L2 red.v4.f16x2.

#define NSEG     2048
#define PIX      (1024 * 1024)
#define TPB      512
#define NBLK     296
#define TOTG     (PIX / 4)             // 262144 pixel-groups of 4
#define SPAIRS   12                    // f16x2 units per px in smem (24 ch)
#define LUNITS   20                    // f16x2 units per px on L2 (40 ch)
#define SMEM_U32 (SPAIRS * NSEG)       // 24576 u32 = 96KB

__device__ __half2 g_sumh[NSEG * LUNITS];            // [seg][unit], L2 RED target
__device__ float2  g_sc[NSEG];                       // (ssq, count)
__device__ float   g_s2[NSEG];                       // sum over ch of (seg sum)^2
__device__ __half2 g_part[(size_t)NBLK * SMEM_U32];  // per-block smem hist dumps

__device__ __forceinline__ void red8(__half2* p, __half2 a, __half2 b,
                                     __half2 c, __half2 d) {
    asm volatile("red.global.add.noftz.v4.f16x2 [%0], {%1,%2,%3,%4};"
                 :: "l"(p),
                    "r"(*(const unsigned*)&a), "r"(*(const unsigned*)&b),
                    "r"(*(const unsigned*)&c), "r"(*(const unsigned*)&d)
                 : "memory");
}
__device__ __forceinline__ void red2(float2* p, float a, float b) {
    asm volatile("red.global.add.v2.f32 [%0], {%1, %2};"
                 :: "l"(p), "f"(a), "f"(b) : "memory");
}
__device__ __forceinline__ void red1(float* p, float a) {
    asm volatile("red.global.add.f32 [%0], %1;" :: "l"(p), "f"(a) : "memory");
}

__global__ void zero_kernel() {
    int i = blockIdx.x * blockDim.x + threadIdx.x;
    if (i < NSEG * LUNITS) ((unsigned*)g_sumh)[i] = 0u;
    int j = i - NSEG * LUNITS;
    if (j >= 0 && j < NSEG) { g_sc[j] = make_float2(0.0f, 0.0f); g_s2[j] = 0.0f; }
}

template <int OCT>
__device__ __forceinline__ void do_oct(const float* __restrict__ feats, int p,
                                       const int4 s4, __half2& q0, __half2& q1,
                                       __half2& q2, __half2& q3, __half2* sh) {
    const float* f = feats + (size_t)(OCT * 8) * PIX + p;

    // stage 1: channels 0..3 of this oct (only 4 float4 live)
    __half2 a0, a1, a2, a3, b0, b1, b2, b3;
    {
        const float4 v0 = *(const float4*)(f + 0 * (size_t)PIX);
        const float4 v1 = *(const float4*)(f + 1 * (size_t)PIX);
        const float4 v2 = *(const float4*)(f + 2 * (size_t)PIX);
        const float4 v3 = *(const float4*)(f + 3 * (size_t)PIX);
        a0 = __floats2half2_rn(v0.x, v1.x); b0 = __floats2half2_rn(v2.x, v3.x);
        a1 = __floats2half2_rn(v0.y, v1.y); b1 = __floats2half2_rn(v2.y, v3.y);
        a2 = __floats2half2_rn(v0.z, v1.z); b2 = __floats2half2_rn(v2.z, v3.z);
        a3 = __floats2half2_rn(v0.w, v1.w); b3 = __floats2half2_rn(v2.w, v3.w);
    }
    q0 = __hfma2(a0, a0, q0); q0 = __hfma2(b0, b0, q0);
    q1 = __hfma2(a1, a1, q1); q1 = __hfma2(b1, b1, q1);
    q2 = __hfma2(a2, a2, q2); q2 = __hfma2(b2, b2, q2);
    q3 = __hfma2(a3, a3, q3); q3 = __hfma2(b3, b3, q3);

    // stage 2: channels 4..7 (reuse the float4 registers)
    __half2 c0, c1, c2, c3, d0, d1, d2, d3;
    {
        const float4 v0 = *(const float4*)(f + 4 * (size_t)PIX);
        const float4 v1 = *(const float4*)(f + 5 * (size_t)PIX);
        const float4 v2 = *(const float4*)(f + 6 * (size_t)PIX);
        const float4 v3 = *(const float4*)(f + 7 * (size_t)PIX);
        c0 = __floats2half2_rn(v0.x, v1.x); d0 = __floats2half2_rn(v2.x, v3.x);
        c1 = __floats2half2_rn(v0.y, v1.y); d1 = __floats2half2_rn(v2.y, v3.y);
        c2 = __floats2half2_rn(v0.z, v1.z); d2 = __floats2half2_rn(v2.z, v3.z);
        c3 = __floats2half2_rn(v0.w, v1.w); d3 = __floats2half2_rn(v2.w, v3.w);
    }
    q0 = __hfma2(c0, c0, q0); q0 = __hfma2(d0, d0, q0);
    q1 = __hfma2(c1, c1, q1); q1 = __hfma2(d1, d1, q1);
    q2 = __hfma2(c2, c2, q2); q2 = __hfma2(d2, d2, q2);
    q3 = __hfma2(c3, c3, q3); q3 = __hfma2(d3, d3, q3);

    if (OCT < 3) {
        __half2* h = sh + OCT * 4 * NSEG;
        atomicAdd(h + 0 * NSEG + s4.x, a0); atomicAdd(h + 1 * NSEG + s4.x, b0);
        atomicAdd(h + 2 * NSEG + s4.x, c0); atomicAdd(h + 3 * NSEG + s4.x, d0);
        atomicAdd(h + 0 * NSEG + s4.y, a1); atomicAdd(h + 1 * NSEG + s4.y, b1);
        atomicAdd(h + 2 * NSEG + s4.y, c1); atomicAdd(h + 3 * NSEG + s4.y, d1);
        atomicAdd(h + 0 * NSEG + s4.z, a2); atomicAdd(h + 1 * NSEG + s4.z, b2);
        atomicAdd(h + 2 * NSEG + s4.z, c2); atomicAdd(h + 3 * NSEG + s4.z, d2);
        atomicAdd(h + 0 * NSEG + s4.w, a3); atomicAdd(h + 1 * NSEG + s4.w, b3);
        atomicAdd(h + 2 * NSEG + s4.w, c3); atomicAdd(h + 3 * NSEG + s4.w, d3);
    } else {
        red8(&g_sumh[(size_t)s4.x * LUNITS + (OCT - 3) * 4], a0, b0, c0, d0);
        red8(&g_sumh[(size_t)s4.y * LUNITS + (OCT - 3) * 4], a1, b1, c1, d1);
        red8(&g_sumh[(size_t)s4.z * LUNITS + (OCT - 3) * 4], a2, b2, c2, d2);
        red8(&g_sumh[(size_t)s4.w * LUNITS + (OCT - 3) * 4], a3, b3, c3, d3);
    }
}

__global__ __launch_bounds__(TPB, 2)
void accum_kernel(const int* __restrict__ sp, const float* __restrict__ feats) {
    extern __shared__ __half2 sh[];    // [SPAIRS][NSEG]

    {   // zero smem hist
        uint4* z = (uint4*)sh;
        #pragma unroll
        for (int i = threadIdx.x; i < SMEM_U32 / 4; i += TPB)
            z[i] = make_uint4(0u, 0u, 0u, 0u);
    }
    __syncthreads();

    const int gstart = (int)(((long long)blockIdx.x       * TOTG) / NBLK);
    const int gend   = (int)(((long long)(blockIdx.x + 1) * TOTG) / NBLK);

    for (int g = gstart + threadIdx.x; g < gend; g += TPB) {
        const int p = g * 4;
        const int4 s4 = *(const int4*)(sp + p);
        __half2 q0 = __float2half2_rn(0.0f), q1 = q0, q2 = q0, q3 = q0;

        do_oct<0>(feats, p, s4, q0, q1, q2, q3, sh);
        do_oct<1>(feats, p, s4, q0, q1, q2, q3, sh);
        do_oct<2>(feats, p, s4, q0, q1, q2, q3, sh);
        do_oct<3>(feats, p, s4, q0, q1, q2, q3, sh);
        do_oct<4>(feats, p, s4, q0, q1, q2, q3, sh);
        do_oct<5>(feats, p, s4, q0, q1, q2, q3, sh);
        do_oct<6>(feats, p, s4, q0, q1, q2, q3, sh);
        do_oct<7>(feats, p, s4, q0, q1, q2, q3, sh);

        red2(&g_sc[s4.x], __low2float(q0) + __high2float(q0), 1.0f);
        red2(&g_sc[s4.y], __low2float(q1) + __high2float(q1), 1.0f);
        red2(&g_sc[s4.z], __low2float(q2) + __high2float(q2), 1.0f);
        red2(&g_sc[s4.w], __low2float(q3) + __high2float(q3), 1.0f);
    }
    __syncthreads();

    // flush smem hist to per-block slab with plain vector stores
    const uint4* src = (const uint4*)sh;
    uint4* dst = (uint4*)(g_part + (size_t)blockIdx.x * SMEM_U32);
    #pragma unroll
    for (int i = threadIdx.x; i < SMEM_U32 / 4; i += TPB)
        dst[i] = src[i];
}

__global__ void reduce_kernel() {
    const int i = blockIdx.x * blockDim.x + threadIdx.x;
    if (i < SMEM_U32) {
        const int seg = i & (NSEG - 1);
        float a0 = 0.f, a1 = 0.f, b0 = 0.f, b1 = 0.f;
        #pragma unroll 4
        for (int b = 0; b < NBLK; b += 2) {
            const float2 u = __half22float2(g_part[(size_t)b * SMEM_U32 + i]);
            const float2 v = __half22float2(g_part[(size_t)(b + 1) * SMEM_U32 + i]);
            a0 += u.x; a1 += u.y; b0 += v.x; b1 += v.y;
        }
        const float sx = a0 + b0, sy = a1 + b1;
        red1(&g_s2[seg], sx * sx + sy * sy);
    } else {
        const int j = i - SMEM_U32;
        if (j < NSEG * LUNITS) {
            const int seg = j / LUNITS;
            const float2 s = __half22float2(g_sumh[j]);
            red1(&g_s2[seg], s.x * s.x + s.y * s.y);
        }
    }
}

__global__ void finalize_kernel(float* __restrict__ out) {
    __shared__ float red_loss[1024];
    __shared__ float red_cnt[1024];
    const int tid = threadIdx.x;
    float loss = 0.0f, nz = 0.0f;
    #pragma unroll
    for (int seg = tid; seg < NSEG; seg += 1024) {
        const float2 sc = g_sc[seg];
        const float n   = sc.y;
        const float nn  = fmaxf(n, 1.0f);
        const float var_sum = sc.x - g_s2[seg] / nn;
        const float per_seg = var_sum / (64.0f * nn);
        if (n >= 2.0f) loss += per_seg;
        if (n > 0.0f)  nz += 1.0f;
    }
    red_loss[tid] = loss;
    red_cnt[tid]  = nz;
    __syncthreads();
    for (int s = 512; s > 0; s >>= 1) {
        if (tid < s) {
            red_loss[tid] += red_loss[tid + s];
            red_cnt[tid]  += red_cnt[tid + s];
        }
        __syncthreads();
    }
    if (tid == 0) out[0] = red_loss[0] / red_cnt[0];
}

extern "C" void kernel_launch(void* const* d_in, const int* in_sizes, int n_in,
                              void* d_out, int out_size) {
    const int* sp;
    const float* feats;
    if (in_sizes[0] == 2 * 1024 * 1024) {
        sp    = (const int*)d_in[0];
        feats = (const float*)d_in[1];
    } else {
        sp    = (const int*)d_in[1];
        feats = (const float*)d_in[0];
    }

    const int smem_bytes = SMEM_U32 * 4;   // 98304
    cudaFuncSetAttribute(accum_kernel,
                         cudaFuncAttributeMaxDynamicSharedMemorySize, smem_bytes);

    const int zero_total = NSEG * LUNITS + NSEG;
    zero_kernel<<<(zero_total + 255) / 256, 256>>>();

    accum_kernel<<<NBLK, TPB, smem_bytes>>>(sp, feats);

    const int red_total = SMEM_U32 + NSEG * LUNITS;
    reduce_kernel<<<(red_total + 255) / 256, 256>>>();

    finalize_kernel<<<1, 1024>>>((float*)d_out);
}